// round 14
// baseline (speedup 1.0000x reference)
#include <cuda_runtime.h>
#include <cstdint>

#define NN 100000
#define DD 128
#define EE 1600000
#define ND (NN * DD)
#define MBLK 782

// ---------------- scratch ----------------
__device__ float g_h[ND];
__device__ float g_agg[ND];
__device__ float g_M[3 * 384 * 128];   // M_l[j][t] = sum_k W_ih[j,k] * W_l[t,k]
__device__ int   g_src[EE];
__device__ int   g_dst[EE];
__device__ int   g_esrc[EE];
__device__ float g_ew[EE];
__device__ int   g_deg[NN];
__device__ int   g_eoff[NN + 1];
__device__ int   g_epos[NN];
__device__ int   g_is64;

// ---------------- f32x2 helpers ----------------
__device__ __forceinline__ unsigned long long pack2(float x, float y) {
    unsigned long long r;
    asm("mov.b64 %0, {%1, %2};" : "=l"(r) : "f"(x), "f"(y));
    return r;
}
__device__ __forceinline__ void fma2(unsigned long long& d, unsigned long long a, unsigned long long b) {
    asm("fma.rn.f32x2 %0, %1, %2, %0;" : "+l"(d) : "l"(a), "l"(b));
}
__device__ __forceinline__ float2 unpack2(unsigned long long v) {
    float2 f;
    asm("mov.b64 {%0, %1}, %2;" : "=f"(f.x), "=f"(f.y) : "l"(v));
    return f;
}
__device__ __forceinline__ float sigm(float x) { return 1.f / (1.f + expf(-x)); }

// ---------------- utility kernels ----------------
__global__ void copy4_kernel(float4* __restrict__ dst, const float4* __restrict__ src, int n4) {
    int i = blockIdx.x * blockDim.x + threadIdx.x;
    if (i < n4) dst[i] = src[i];
}
__global__ void detect_kernel(const unsigned int* __restrict__ p) {
    if (blockIdx.x == 0 && threadIdx.x == 0) {
        unsigned long long s = 0;
        for (int i = 1; i < 2048; i += 2) s += p[i];
        g_is64 = (s == 0ull) ? 1 : 0;
    }
}
__global__ void conv_edges_kernel(const int* __restrict__ p) {
    int i = blockIdx.x * blockDim.x + threadIdx.x;
    if (i >= EE) return;
    if (g_is64) { g_src[i] = p[2 * i]; g_dst[i] = p[2 * (EE + i)]; }
    else        { g_src[i] = p[i];     g_dst[i] = p[EE + i]; }
}

// ---------------- CSR build (per call; edges are call-constant) ----------------
__global__ void zero_deg_kernel() {
    int i = blockIdx.x * blockDim.x + threadIdx.x;
    if (i < NN) g_deg[i] = 0;
}
__global__ void hist_kernel() {
    int i = blockIdx.x * blockDim.x + threadIdx.x;
    if (i < EE) atomicAdd(&g_deg[g_dst[i]], 1);
}
__global__ void scan_kernel() {
    __shared__ int ssum[256];
    int t = threadIdx.x;
    int b = t * 392;
    int e = min(b + 392, NN);
    int s = 0;
    for (int n = b; n < e; n++) s += g_deg[n];
    ssum[t] = s;
    __syncthreads();
    if (t == 0) {
        int run = 0;
        for (int i = 0; i < 256; i++) { int v = ssum[i]; ssum[i] = run; run += v; }
    }
    __syncthreads();
    int run = ssum[t];
    for (int n = b; n < e; n++) {
        g_eoff[n] = run;
        g_epos[n] = run;
        run += g_deg[n];
    }
    if (t == 255) g_eoff[NN] = run;
}
__global__ void fill_kernel(const float* __restrict__ ea) {
    int i = blockIdx.x * blockDim.x + threadIdx.x;
    if (i >= EE) return;
    int d = g_dst[i];
    int slot = atomicAdd(&g_epos[d], 1);
    g_esrc[slot] = g_src[i];
    g_ew[slot] = ea[i];
}

// ---------------- M_l = W_ih @ W_l^T ----------------
__global__ void mcomb_kernel(const float* __restrict__ W, const float* __restrict__ W_ih) {
    int idx = blockIdx.x * blockDim.x + threadIdx.x;
    if (idx >= 384 * 128) return;
    int l = blockIdx.y;
    int j = idx >> 7, t = idx & 127;
    const float* wi = W_ih + j * 128;
    const float* wl = W + l * 128 * 128 + t * 128;
    float s = 0.f;
#pragma unroll 8
    for (int k = 0; k < 128; k++) s = fmaf(__ldg(&wi[k]), __ldg(&wl[k]), s);
    g_M[(l * 384 + j) * 128 + t] = s;
}

// ---------------- gather: agg[n] = sum_{e: dst=n} h[src_e] * w_e (warp per node) ----------------
__global__ void gather_kernel() {
    int gw = (blockIdx.x * blockDim.x + threadIdx.x) >> 5;
    int lane = threadIdx.x & 31;
    if (gw >= NN) return;
    int beg = g_eoff[gw], end = g_eoff[gw + 1];
    float4 acc = make_float4(0.f, 0.f, 0.f, 0.f);
    for (int e = beg; e < end; e++) {
        int s = __ldg(&g_esrc[e]);
        float w = __ldg(&g_ew[e]);
        float4 v = *((const float4*)g_h + (size_t)s * 32 + lane);
        acc.x = fmaf(v.x, w, acc.x);
        acc.y = fmaf(v.y, w, acc.y);
        acc.z = fmaf(v.z, w, acc.z);
        acc.w = fmaf(v.w, w, acc.w);
    }
    *((float4*)g_agg + (size_t)gw * 32 + lane) = acc;
}

// ---------------- one K=128 GEMM pass: acc += A_rows(m0..m0+127) @ Bt(128 rows)^T ----------------
__device__ __forceinline__ void gemm_pass(float* As, unsigned long long* Bsd,
                                          unsigned long long acc[8][4],
                                          const float* __restrict__ Arow,
                                          const float* __restrict__ Brow,
                                          bool aok, int lm, int l0, int tx, int ty) {
    const float4 z4 = make_float4(0.f, 0.f, 0.f, 0.f);
    float4 a0 = aok ? *(const float4*)&Arow[l0]     : z4;
    float4 a1 = aok ? *(const float4*)&Arow[l0 + 4] : z4;
    float4 b0 = *(const float4*)&Brow[l0];
    float4 b1 = *(const float4*)&Brow[l0 + 4];

    for (int c = 0; c < 8; c++) {
        __syncthreads();   // protect buffers from previous chunk/pass readers
        As[(l0 + 0) * 132 + lm] = a0.x; As[(l0 + 1) * 132 + lm] = a0.y;
        As[(l0 + 2) * 132 + lm] = a0.z; As[(l0 + 3) * 132 + lm] = a0.w;
        As[(l0 + 4) * 132 + lm] = a1.x; As[(l0 + 5) * 132 + lm] = a1.y;
        As[(l0 + 6) * 132 + lm] = a1.z; As[(l0 + 7) * 132 + lm] = a1.w;
        Bsd[(l0 + 0) * 132 + lm] = pack2(b0.x, b0.x); Bsd[(l0 + 1) * 132 + lm] = pack2(b0.y, b0.y);
        Bsd[(l0 + 2) * 132 + lm] = pack2(b0.z, b0.z); Bsd[(l0 + 3) * 132 + lm] = pack2(b0.w, b0.w);
        Bsd[(l0 + 4) * 132 + lm] = pack2(b1.x, b1.x); Bsd[(l0 + 5) * 132 + lm] = pack2(b1.y, b1.y);
        Bsd[(l0 + 6) * 132 + lm] = pack2(b1.z, b1.z); Bsd[(l0 + 7) * 132 + lm] = pack2(b1.w, b1.w);
        __syncthreads();

        if (c < 7) {
            int kn = (c + 1) * 16;
            a0 = aok ? *(const float4*)&Arow[kn + l0]     : z4;
            a1 = aok ? *(const float4*)&Arow[kn + l0 + 4] : z4;
            b0 = *(const float4*)&Brow[kn + l0];
            b1 = *(const float4*)&Brow[kn + l0 + 4];
        }

#pragma unroll
        for (int kk = 0; kk < 16; kk++) {
            ulonglong2 pa0 = *(const ulonglong2*)&As[kk * 132 + ty * 8];
            ulonglong2 pa1 = *(const ulonglong2*)&As[kk * 132 + ty * 8 + 4];
            unsigned long long ap0 = pa0.x, ap1 = pa0.y, ap2 = pa1.x, ap3 = pa1.y;
#pragma unroll
            for (int jj = 0; jj < 8; jj++) {
                unsigned long long b2 = Bsd[kk * 132 + tx + 16 * jj];
                fma2(acc[jj][0], ap0, b2);
                fma2(acc[jj][1], ap1, b2);
                fma2(acc[jj][2], ap2, b2);
                fma2(acc[jj][3], ap3, b2);
            }
        }
    }
}

// ---------------- fused: h_new = GRU(agg@M^T + b_ih, h@W_hh^T + b_hh, h) ----------------
// SMEM: As [16][132] f32 (8448) + Bsd [16][132] u64 (16896) + 3 stages [64][256] f32 (196608)
#define STG_OFF 25344
#define SMEM_FUSED (25344 + 3 * 65536)   // 221952

__global__ __launch_bounds__(256) void fused_gemm_gru_kernel(const float* __restrict__ Ml,
                                                             const float* __restrict__ W_hh,
                                                             const float* __restrict__ b_ih,
                                                             const float* __restrict__ b_hh,
                                                             float* __restrict__ hout) {
    extern __shared__ char smem[];
    float* As = (float*)smem;
    unsigned long long* Bsd = (unsigned long long*)(smem + 8448);
    float* stg = (float*)(smem + STG_OFF);    // [gate][e][tid]

    const int tid = threadIdx.x;
    const int tx = tid & 15, ty = tid >> 4;
    const int lm = tid >> 1;
    const int l0 = ((tid * 2) & 3) * 4;
    const int m0 = blockIdx.x * 128;
    const bool aok = (m0 + lm) < NN;

    const float* AggRow = g_agg + (size_t)(m0 + lm) * 128;
    const float* HRow   = g_h   + (size_t)(m0 + lm) * 128;

    unsigned long long acc[8][4];

    for (int gate = 0; gate < 3; gate++) {
        // ---- pass 1: agg @ M_gate^T  (bias: b_ih[gate]; for r,z also b_hh[gate]) ----
#pragma unroll
        for (int jj = 0; jj < 8; jj++) {
            int col = gate * 128 + tx + 16 * jj;
            float bj = __ldg(&b_ih[col]) + (gate < 2 ? __ldg(&b_hh[col]) : 0.f);
            unsigned long long b2 = pack2(bj, bj);
#pragma unroll
            for (int p = 0; p < 4; p++) acc[jj][p] = b2;
        }
        gemm_pass(As, Bsd, acc, AggRow, Ml + (size_t)gate * 16384 + lm * 128, aok, lm, l0, tx, ty);

        if (gate == 2) {
            // stash i_n to stage 2, re-init acc with b_hh[n]
#pragma unroll
            for (int jj = 0; jj < 8; jj++)
#pragma unroll
                for (int p = 0; p < 4; p++) {
                    float2 v = unpack2(acc[jj][p]);
                    int e = jj * 8 + p * 2;
                    stg[2 * 16384 + e * 256 + tid] = v.x;
                    stg[2 * 16384 + (e + 1) * 256 + tid] = v.y;
                }
#pragma unroll
            for (int jj = 0; jj < 8; jj++) {
                float bj = __ldg(&b_hh[256 + tx + 16 * jj]);
                unsigned long long b2 = pack2(bj, bj);
#pragma unroll
                for (int p = 0; p < 4; p++) acc[jj][p] = b2;
            }
        }

        // ---- pass 2: h @ W_hh_gate^T ----
        gemm_pass(As, Bsd, acc, HRow, W_hh + (size_t)gate * 16384 + lm * 128, aok, lm, l0, tx, ty);

        if (gate < 2) {
            // r or z: sigmoid -> stage (thread-private, no sync needed)
#pragma unroll
            for (int jj = 0; jj < 8; jj++)
#pragma unroll
                for (int p = 0; p < 4; p++) {
                    float2 v = unpack2(acc[jj][p]);
                    int e = jj * 8 + p * 2;
                    stg[gate * 16384 + e * 256 + tid] = sigm(v.x);
                    stg[gate * 16384 + (e + 1) * 256 + tid] = sigm(v.y);
                }
        }
    }

    // ---- combine: n = tanh(i_n + r*h_n); h_new = (1-z)*n + z*h ----
    // Safe to overwrite g_h rows [m0, m0+128): only this CTA reads them, and all passes are done.
#pragma unroll
    for (int jj = 0; jj < 8; jj++) {
        int col = tx + 16 * jj;
#pragma unroll
        for (int p = 0; p < 4; p++) {
            float2 hn = unpack2(acc[jj][p]);
#pragma unroll
            for (int q = 0; q < 2; q++) {
                int e = jj * 8 + p * 2 + q;
                int row = m0 + ty * 8 + 2 * p + q;
                if (row < NN) {
                    float r = stg[e * 256 + tid];
                    float z = stg[16384 + e * 256 + tid];
                    float in_ = stg[2 * 16384 + e * 256 + tid];
                    float n = tanhf(in_ + r * (q ? hn.y : hn.x));
                    float hv = g_h[(size_t)row * 128 + col];
                    float hnew = (1.f - z) * n + z * hv;
                    hout[(size_t)row * 128 + col] = hnew;
                    if (hout != g_h) g_h[(size_t)row * 128 + col] = hnew;  // keep consistent (unused after)
                }
            }
        }
    }
}

// ---------------- launch ----------------
extern "C" void kernel_launch(void* const* d_in, const int* in_sizes, int n_in,
                              void* d_out, int out_size) {
    const float* x    = (const float*)d_in[0];
    const int*   ei   = (const int*)d_in[1];
    const float* ea   = (const float*)d_in[2];
    const float* W    = (const float*)d_in[3];
    const float* W_ih = (const float*)d_in[4];
    const float* W_hh = (const float*)d_in[5];
    const float* b_ih = (const float*)d_in[6];
    const float* b_hh = (const float*)d_in[7];
    float* out = (float*)d_out;

    cudaFuncSetAttribute(fused_gemm_gru_kernel, cudaFuncAttributeMaxDynamicSharedMemorySize, SMEM_FUSED);

    float *ph, *pM;
    cudaGetSymbolAddress((void**)&ph, g_h);
    cudaGetSymbolAddress((void**)&pM, g_M);

    const int n4 = ND / 4;

    detect_kernel<<<1, 32>>>((const unsigned int*)ei);
    conv_edges_kernel<<<EE / 256, 256>>>(ei);
    copy4_kernel<<<n4 / 256, 256>>>((float4*)ph, (const float4*)x, n4);

    // CSR build (once per call)
    zero_deg_kernel<<<(NN + 255) / 256, 256>>>();
    hist_kernel<<<EE / 256, 256>>>();
    scan_kernel<<<1, 256>>>();
    fill_kernel<<<EE / 256, 256>>>(ea);

    // combined weights M_l = W_ih @ W_l^T for all layers
    mcomb_kernel<<<dim3(192, 3), 256>>>(W, W_ih);

    for (int l = 0; l < 3; l++) {
        gather_kernel<<<(NN * 32 + 255) / 256, 256>>>();
        float* hout = (l == 2) ? out : ph;
        fused_gemm_gru_kernel<<<MBLK, 256, SMEM_FUSED>>>(pM + (size_t)l * 384 * 128, W_hh, b_ih, b_hh, hout);
    }
}